// round 1
// baseline (speedup 1.0000x reference)
#include <cuda_runtime.h>
#include <cstdint>
#include <cstddef>

// Problem constants
#define B_ 64
#define T_ 1024
#define I_ 128
#define H_ 256

#define NCTA 96
#define L1CTAS 32
#define THREADS 256

// Inputs (metadata order): x, Wf1, bf1, Wc1, bc1, Wf2, bf2, Wc2, bc2
// Output: y2 [B,T,H] (B*T*H floats) then hidden [2,B,H] (2*B*H floats)

// -------- device scratch (allocation-free: __device__ globals) --------
__device__ float g_xpre[(size_t)B_ * T_ * 512];   // [b*T+t][0:256]=f-pre, [256:512]=c-pre (x part + bias)
__device__ float g_h1[2][B_ * H_];                // ping-pong h1
__device__ float g_h2[2][B_ * H_];                // ping-pong h2
__device__ unsigned g_count;
__device__ unsigned g_gen;

// ============================================================
// Phase 1: x-projection GEMM  (65536 x 128) @ (128 x 512) + bias
// ============================================================
__global__ void __launch_bounds__(256) xproj_kernel(
    const float* __restrict__ x,
    const float* __restrict__ Wf1, const float* __restrict__ bf1,
    const float* __restrict__ Wc1, const float* __restrict__ bc1)
{
    __shared__ float As[64][68];
    __shared__ float Bs[64][68];
    const int bm = blockIdx.x;          // 1024 row tiles of 64
    const int bn = blockIdx.y;          // 8 col tiles of 64
    const int tid = threadIdx.x;
    const int tx = tid & 15, ty = tid >> 4;

    const float* W; const float* bias; int jb;
    if (bn < 4) { W = Wf1; bias = bf1; jb = bn * 64; }
    else        { W = Wc1; bias = bc1; jb = (bn - 4) * 64; }

    float acc[4][4];
#pragma unroll
    for (int i = 0; i < 4; ++i)
#pragma unroll
        for (int j = 0; j < 4; ++j) acc[i][j] = 0.f;

    for (int k0 = 0; k0 < 128; k0 += 64) {
#pragma unroll
        for (int i = 0; i < 4; ++i) {
            int idx = tid + i * 256;
            int r = idx >> 4, kv = idx & 15;
            float4 v = *(const float4*)(x + (size_t)(bm * 64 + r) * 128 + k0 + kv * 4);
            *(float4*)&As[r][kv * 4] = v;
        }
#pragma unroll
        for (int i = 0; i < 4; ++i) {
            int idx = tid + i * 256;
            int kk = idx >> 4, cv = idx & 15;
            float4 v = *(const float4*)(W + (size_t)(k0 + kk) * 256 + jb + cv * 4);
            *(float4*)&Bs[kk][cv * 4] = v;
        }
        __syncthreads();
#pragma unroll 16
        for (int kk = 0; kk < 64; ++kk) {
            float a0 = As[ty * 4 + 0][kk];
            float a1 = As[ty * 4 + 1][kk];
            float a2 = As[ty * 4 + 2][kk];
            float a3 = As[ty * 4 + 3][kk];
            float4 bv = *(const float4*)&Bs[kk][tx * 4];
            acc[0][0] = fmaf(a0, bv.x, acc[0][0]);
            acc[0][1] = fmaf(a0, bv.y, acc[0][1]);
            acc[0][2] = fmaf(a0, bv.z, acc[0][2]);
            acc[0][3] = fmaf(a0, bv.w, acc[0][3]);
            acc[1][0] = fmaf(a1, bv.x, acc[1][0]);
            acc[1][1] = fmaf(a1, bv.y, acc[1][1]);
            acc[1][2] = fmaf(a1, bv.z, acc[1][2]);
            acc[1][3] = fmaf(a1, bv.w, acc[1][3]);
            acc[2][0] = fmaf(a2, bv.x, acc[2][0]);
            acc[2][1] = fmaf(a2, bv.y, acc[2][1]);
            acc[2][2] = fmaf(a2, bv.z, acc[2][2]);
            acc[2][3] = fmaf(a2, bv.w, acc[2][3]);
            acc[3][0] = fmaf(a3, bv.x, acc[3][0]);
            acc[3][1] = fmaf(a3, bv.y, acc[3][1]);
            acc[3][2] = fmaf(a3, bv.z, acc[3][2]);
            acc[3][3] = fmaf(a3, bv.w, acc[3][3]);
        }
        __syncthreads();
    }
#pragma unroll
    for (int i = 0; i < 4; ++i) {
        int r = bm * 64 + ty * 4 + i;
        float4 o;
        o.x = acc[i][0] + bias[jb + tx * 4 + 0];
        o.y = acc[i][1] + bias[jb + tx * 4 + 1];
        o.z = acc[i][2] + bias[jb + tx * 4 + 2];
        o.w = acc[i][3] + bias[jb + tx * 4 + 3];
        *(float4*)&g_xpre[(size_t)r * 512 + bn * 64 + tx * 4] = o;
    }
}

// ============================================================
// Init: zero h state + barrier counters (graph-replay safe)
// ============================================================
__global__ void init_kernel()
{
    int i = blockIdx.x * blockDim.x + threadIdx.x;
    if (i < B_ * H_) {
        g_h1[0][i] = 0.f;
        g_h2[0][i] = 0.f;
        g_h2[1][i] = 0.f;
    }
    if (i == 0) { g_count = 0; g_gen = 0; }
}

// ============================================================
// Phase 2: persistent pipelined recurrence
// ============================================================
__device__ __forceinline__ void grid_barrier(unsigned target)
{
    __syncthreads();
    if (threadIdx.x == 0) {
        __threadfence();
        unsigned t = atomicAdd(&g_count, 1);
        if (t == NCTA - 1) {
            g_count = 0;
            __threadfence();
            atomicExch(&g_gen, target);
        } else {
            volatile unsigned* gp = &g_gen;
            while (*gp < target) { __nanosleep(32); }
        }
    }
    __syncthreads();
}

#define L1_STEP(i, WFS, WCS) { \
    float2 hv = *(const float2*)&hs[(k4 + (i)) * 64 + b0]; \
    accf0 = fmaf(hv.x, (WFS), accf0); \
    accf1 = fmaf(hv.y, (WFS), accf1); \
    accc0 = fmaf(hv.x, (WCS), accc0); \
    accc1 = fmaf(hv.y, (WCS), accc1); }

#define L2_STEP(i, WFS, WCS) { \
    float hv = hs[(k4 + (i)) * 64 + bb]; \
    accf = fmaf(hv, (WFS), accf); \
    accc = fmaf(hv, (WCS), accc); }

__global__ void __launch_bounds__(THREADS, 1) recur_kernel(
    const float* __restrict__ Wf1, const float* __restrict__ Wc1,
    const float* __restrict__ Wf2, const float* __restrict__ bf2,
    const float* __restrict__ Wc2, const float* __restrict__ bc2,
    float* __restrict__ out)
{
    __shared__ float hs[128 * 64];     // transposed h chunk: hs[k][b], 32KB
    __shared__ float wsm[16 * 256];    // weight slice (16KB): L1 16x256, L2 8x512

    const int tid = threadIdx.x;
    const int warp = tid >> 5, lane = tid & 31;
    const int cid = blockIdx.x;

    if (cid < L1CTAS) {
        // ---------------- Layer-1 CTA: 8 cols, both gates, all 64 batch ----------------
        const int j0 = cid * 8;
        for (int i = tid; i < 16 * 256; i += THREADS) {
            int o = i >> 8, k = i & 255;
            int j = j0 + (o >> 1);
            wsm[i] = (o & 1) ? Wc1[(size_t)(I_ + k) * H_ + j] : Wf1[(size_t)(I_ + k) * H_ + j];
        }
        const int j = j0 + warp;
        const int b0 = lane * 2, b1 = lane * 2 + 1;

        for (int t = 0; t <= T_; ++t) {
            if (t < T_) {
                const float* hsrc = g_h1[t & 1];
                float accf0 = 0.f, accf1 = 0.f, accc0 = 0.f, accc1 = 0.f;
#pragma unroll
                for (int p = 0; p < 2; ++p) {
                    __syncthreads();
                    {
                        int b = tid & 63, kb = (tid >> 6) * 32;
                        const float4* src = (const float4*)(hsrc + b * H_ + p * 128 + kb);
#pragma unroll
                        for (int i = 0; i < 8; ++i) {
                            float4 v = __ldcg(src + i);
                            int k = kb + i * 4;
                            hs[(k + 0) * 64 + b] = v.x;
                            hs[(k + 1) * 64 + b] = v.y;
                            hs[(k + 2) * 64 + b] = v.z;
                            hs[(k + 3) * 64 + b] = v.w;
                        }
                    }
                    __syncthreads();
                    const float* wf = &wsm[(warp * 2 + 0) * 256 + p * 128];
                    const float* wc = &wsm[(warp * 2 + 1) * 256 + p * 128];
#pragma unroll 8
                    for (int k4 = 0; k4 < 128; k4 += 4) {
                        float4 wfv = *(const float4*)(wf + k4);
                        float4 wcv = *(const float4*)(wc + k4);
                        L1_STEP(0, wfv.x, wcv.x);
                        L1_STEP(1, wfv.y, wcv.y);
                        L1_STEP(2, wfv.z, wcv.z);
                        L1_STEP(3, wfv.w, wcv.w);
                    }
                }
                // finalize gates
                size_t r0 = ((size_t)b0 * T_ + t) * 512;
                size_t r1 = ((size_t)b1 * T_ + t) * 512;
                float pf0 = accf0 + g_xpre[r0 + j];
                float pf1 = accf1 + g_xpre[r1 + j];
                float pc0 = accc0 + g_xpre[r0 + 256 + j];
                float pc1 = accc1 + g_xpre[r1 + 256 + j];
                float f0 = 1.f / (1.f + expf(-pf0));
                float f1 = 1.f / (1.f + expf(-pf1));
                float c0 = tanhf(pc0);
                float c1 = tanhf(pc1);
                float ho0 = __ldcg(hsrc + b0 * H_ + j);
                float ho1 = __ldcg(hsrc + b1 * H_ + j);
                float hn0 = f0 * ho0 + (1.f - f0) * c0;
                float hn1 = f1 * ho1 + (1.f - f1) * c1;
                float* hdst = g_h1[(t + 1) & 1];
                hdst[b0 * H_ + j] = hn0;
                hdst[b1 * H_ + j] = hn1;
                if (t == T_ - 1) {
                    out[(size_t)B_ * T_ * H_ + b0 * H_ + j] = hn0;
                    out[(size_t)B_ * T_ * H_ + b1 * H_ + j] = hn1;
                }
            }
            grid_barrier((unsigned)(t + 1));
        }
    } else {
        // ---------------- Layer-2 CTA: 4 cols, both gates; warp = (col, batch-half) ----------------
        const int m = cid - L1CTAS;          // 0..63
        const int j0 = m * 4;
        for (int i = tid; i < 8 * 512; i += THREADS) {
            int o = i >> 9, k = i & 511;
            int j = j0 + (o >> 1);
            wsm[i] = (o & 1) ? Wc2[(size_t)k * H_ + j] : Wf2[(size_t)k * H_ + j];
        }
        const int j = j0 + (warp >> 1);
        const int bb = (warp & 1) * 32 + lane;
        const float biasf = __ldg(bf2 + j);
        const float biasc = __ldg(bc2 + j);

        for (int t = 0; t <= T_; ++t) {
            if (t >= 1) {
                const float* s1 = g_h1[t & 1];   // = y1[t-1]
                const float* s2 = g_h2[t & 1];
                float accf = 0.f, accc = 0.f;
#pragma unroll
                for (int p = 0; p < 4; ++p) {
                    const float* hsrc = (p < 2) ? s1 : s2;
                    const int koff = (p & 1) * 128;
                    __syncthreads();
                    {
                        int b = tid & 63, kb = (tid >> 6) * 32;
                        const float4* src = (const float4*)(hsrc + b * H_ + koff + kb);
#pragma unroll
                        for (int i = 0; i < 8; ++i) {
                            float4 v = __ldcg(src + i);
                            int k = kb + i * 4;
                            hs[(k + 0) * 64 + b] = v.x;
                            hs[(k + 1) * 64 + b] = v.y;
                            hs[(k + 2) * 64 + b] = v.z;
                            hs[(k + 3) * 64 + b] = v.w;
                        }
                    }
                    __syncthreads();
                    const float* wf = &wsm[((warp >> 1) * 2 + 0) * 512 + p * 128];
                    const float* wc = &wsm[((warp >> 1) * 2 + 1) * 512 + p * 128];
#pragma unroll 8
                    for (int k4 = 0; k4 < 128; k4 += 4) {
                        float4 wfv = *(const float4*)(wf + k4);
                        float4 wcv = *(const float4*)(wc + k4);
                        L2_STEP(0, wfv.x, wcv.x);
                        L2_STEP(1, wfv.y, wcv.y);
                        L2_STEP(2, wfv.z, wcv.z);
                        L2_STEP(3, wfv.w, wcv.w);
                    }
                }
                float pf = accf + biasf;
                float pc = accc + biasc;
                float f = 1.f / (1.f + expf(-pf));
                float c = tanhf(pc);
                float ho = __ldcg(s2 + bb * H_ + j);
                float hn = f * ho + (1.f - f) * c;
                g_h2[(t + 1) & 1][bb * H_ + j] = hn;
                out[((size_t)bb * T_ + (t - 1)) * H_ + j] = hn;
                if (t == T_) {
                    out[(size_t)B_ * T_ * H_ + (size_t)B_ * H_ + bb * H_ + j] = hn;
                }
            }
            grid_barrier((unsigned)(t + 1));
        }
    }
}

// ============================================================
extern "C" void kernel_launch(void* const* d_in, const int* in_sizes, int n_in,
                              void* d_out, int out_size)
{
    const float* x   = (const float*)d_in[0];
    const float* Wf1 = (const float*)d_in[1];
    const float* bf1 = (const float*)d_in[2];
    const float* Wc1 = (const float*)d_in[3];
    const float* bc1 = (const float*)d_in[4];
    const float* Wf2 = (const float*)d_in[5];
    const float* bf2 = (const float*)d_in[6];
    const float* Wc2 = (const float*)d_in[7];
    const float* bc2 = (const float*)d_in[8];
    float* out = (float*)d_out;

    xproj_kernel<<<dim3(1024, 8), 256>>>(x, Wf1, bf1, Wc1, bc1);
    init_kernel<<<64, 256>>>();
    recur_kernel<<<NCTA, THREADS>>>(Wf1, Wc1, Wf2, bf2, Wc2, bc2, out);
}

// round 2
// speedup vs baseline: 2.0232x; 2.0232x over previous
#include <cuda_runtime.h>
#include <cstdint>
#include <cstddef>

// Problem constants
#define B_ 64
#define T_ 1024
#define I_ 128
#define H_ 256

#define L1CTAS 32
#define L2CTAS 64
#define NCTA (L1CTAS + L2CTAS)
#define THREADS 256

// Inputs (metadata order): x, Wf1, bf1, Wc1, bc1, Wf2, bf2, Wc2, bc2
// Output: y2 [B,T,H] then hidden [2,B,H]

// -------- device scratch --------
__device__ __align__(16) float g_xpre[(size_t)B_ * T_ * 512];          // [b*T+t][0:256]=f-pre, [256:512]=c-pre
__device__ __align__(16) float g_y1t[(size_t)(T_ + 1) * H_ * B_];      // transposed h1 history: [t][j][b]
__device__ __align__(16) float g_h2t[2][H_ * B_];                      // transposed h2 ping-pong: [par][j][b]
__device__ unsigned g_cnt1[T_ + 1];
__device__ unsigned g_cnt2[T_ + 1];

// -------- PTX helpers --------
__device__ __forceinline__ uint32_t s2u(const void* p) {
    return (uint32_t)__cvta_generic_to_shared(p);
}
__device__ __forceinline__ void mbar_init(uint32_t a, uint32_t cnt) {
    asm volatile("mbarrier.init.shared.b64 [%0], %1;" :: "r"(a), "r"(cnt) : "memory");
}
__device__ __forceinline__ void mbar_expect(uint32_t a, uint32_t bytes) {
    asm volatile("mbarrier.arrive.expect_tx.shared.b64 _, [%0], %1;" :: "r"(a), "r"(bytes) : "memory");
}
__device__ __forceinline__ void bulk_g2s(uint32_t dst, const void* src, uint32_t bytes, uint32_t mbar) {
    asm volatile("cp.async.bulk.shared::cluster.global.mbarrier::complete_tx::bytes [%0], [%1], %2, [%3];"
                 :: "r"(dst), "l"(src), "r"(bytes), "r"(mbar) : "memory");
}
__device__ __forceinline__ void mbar_wait(uint32_t a, uint32_t parity) {
    asm volatile("{\n\t"
                 ".reg .pred P;\n\t"
                 "W%=:\n\t"
                 "mbarrier.try_wait.parity.shared.b64 P, [%0], %1, 0x989680;\n\t"
                 "@P bra D%=;\n\t"
                 "bra W%=;\n\t"
                 "D%=:\n\t"
                 "}" :: "r"(a), "r"(parity) : "memory");
}
__device__ __forceinline__ void fence_async() {
    asm volatile("fence.proxy.async.shared::cta;" ::: "memory");
}
__device__ __forceinline__ unsigned ld_acq(const unsigned* p) {
    unsigned v;
    asm volatile("ld.global.acquire.gpu.u32 %0, [%1];" : "=r"(v) : "l"(p) : "memory");
    return v;
}
__device__ __forceinline__ void red_add1(unsigned* p) {
    asm volatile("red.release.gpu.global.add.u32 [%0], %1;" :: "l"(p), "r"(1u) : "memory");
}

// ============================================================
// Phase 1: x-projection GEMM  (65536 x 128) @ (128 x 512) + bias
// ============================================================
__global__ void __launch_bounds__(256) xproj_kernel(
    const float* __restrict__ x,
    const float* __restrict__ Wf1, const float* __restrict__ bf1,
    const float* __restrict__ Wc1, const float* __restrict__ bc1)
{
    __shared__ float As[64][68];
    __shared__ float Bs[64][68];
    const int bm = blockIdx.x;
    const int bn = blockIdx.y;
    const int tid = threadIdx.x;
    const int tx = tid & 15, ty = tid >> 4;

    const float* W; const float* bias; int jb;
    if (bn < 4) { W = Wf1; bias = bf1; jb = bn * 64; }
    else        { W = Wc1; bias = bc1; jb = (bn - 4) * 64; }

    float acc[4][4];
#pragma unroll
    for (int i = 0; i < 4; ++i)
#pragma unroll
        for (int j = 0; j < 4; ++j) acc[i][j] = 0.f;

    for (int k0 = 0; k0 < 128; k0 += 64) {
#pragma unroll
        for (int i = 0; i < 4; ++i) {
            int idx = tid + i * 256;
            int r = idx >> 4, kv = idx & 15;
            float4 v = *(const float4*)(x + (size_t)(bm * 64 + r) * 128 + k0 + kv * 4);
            *(float4*)&As[r][kv * 4] = v;
        }
#pragma unroll
        for (int i = 0; i < 4; ++i) {
            int idx = tid + i * 256;
            int kk = idx >> 4, cv = idx & 15;
            float4 v = *(const float4*)(W + (size_t)(k0 + kk) * 256 + jb + cv * 4);
            *(float4*)&Bs[kk][cv * 4] = v;
        }
        __syncthreads();
#pragma unroll 16
        for (int kk = 0; kk < 64; ++kk) {
            float a0 = As[ty * 4 + 0][kk];
            float a1 = As[ty * 4 + 1][kk];
            float a2 = As[ty * 4 + 2][kk];
            float a3 = As[ty * 4 + 3][kk];
            float4 bv = *(const float4*)&Bs[kk][tx * 4];
            acc[0][0] = fmaf(a0, bv.x, acc[0][0]);
            acc[0][1] = fmaf(a0, bv.y, acc[0][1]);
            acc[0][2] = fmaf(a0, bv.z, acc[0][2]);
            acc[0][3] = fmaf(a0, bv.w, acc[0][3]);
            acc[1][0] = fmaf(a1, bv.x, acc[1][0]);
            acc[1][1] = fmaf(a1, bv.y, acc[1][1]);
            acc[1][2] = fmaf(a1, bv.z, acc[1][2]);
            acc[1][3] = fmaf(a1, bv.w, acc[1][3]);
            acc[2][0] = fmaf(a2, bv.x, acc[2][0]);
            acc[2][1] = fmaf(a2, bv.y, acc[2][1]);
            acc[2][2] = fmaf(a2, bv.z, acc[2][2]);
            acc[2][3] = fmaf(a2, bv.w, acc[2][3]);
            acc[3][0] = fmaf(a3, bv.x, acc[3][0]);
            acc[3][1] = fmaf(a3, bv.y, acc[3][1]);
            acc[3][2] = fmaf(a3, bv.z, acc[3][2]);
            acc[3][3] = fmaf(a3, bv.w, acc[3][3]);
        }
        __syncthreads();
    }
#pragma unroll
    for (int i = 0; i < 4; ++i) {
        int r = bm * 64 + ty * 4 + i;
        float4 o;
        o.x = acc[i][0] + bias[jb + tx * 4 + 0];
        o.y = acc[i][1] + bias[jb + tx * 4 + 1];
        o.z = acc[i][2] + bias[jb + tx * 4 + 2];
        o.w = acc[i][3] + bias[jb + tx * 4 + 3];
        *(float4*)&g_xpre[(size_t)r * 512 + bn * 64 + tx * 4] = o;
    }
}

// ============================================================
// Init: zero initial states + counters (graph-replay safe)
// ============================================================
__global__ void init_kernel()
{
    int i = blockIdx.x * blockDim.x + threadIdx.x;   // 16384 threads
    if (i < H_ * B_) {
        g_y1t[i] = 0.f;        // state 0 of layer 1
        g_h2t[0][i] = 0.f;     // state 0 of layer 2
    }
    if (i <= T_) { g_cnt1[i] = 0; g_cnt2[i] = 0; }
}

// ============================================================
// Phase 2: persistent pipelined recurrence (decoupled groups)
// ============================================================
extern __shared__ __align__(16) float hs[];   // L1: 256*64 floats (64KB), L2: 512*64 (128KB), layout [k][b]

__global__ void __launch_bounds__(THREADS, 1) recur_kernel(
    const float* __restrict__ Wf1, const float* __restrict__ Wc1,
    const float* __restrict__ Wf2, const float* __restrict__ bf2,
    const float* __restrict__ Wc2, const float* __restrict__ bc2,
    float* __restrict__ out)
{
    __shared__ float wsm[4096];                    // 16KB weight slice
    __shared__ float xs[2 * 8 * 64];               // L1 only: xpre staging [g][w][b]
    __shared__ __align__(8) unsigned long long mbar[4];

    const int tid = threadIdx.x;
    const int warp = tid >> 5, lane = tid & 31;
    const int cid = blockIdx.x;

    if (tid == 0) {
#pragma unroll
        for (int i = 0; i < 4; ++i) mbar_init(s2u(&mbar[i]), 1);
    }

    if (cid < L1CTAS) {
        // ---------------- Layer-1 CTA: 8 cols, 2 gates, 64 batches ----------------
        const int j0 = cid * 8;
        for (int i = tid; i < 16 * 256; i += THREADS) {
            int o = i >> 8, k = i & 255;
            int j = j0 + (o >> 1);
            wsm[i] = (o & 1) ? Wc1[(size_t)(I_ + k) * H_ + j] : Wf1[(size_t)(I_ + k) * H_ + j];
        }
        __syncthreads();

        const int j = j0 + warp;                       // absolute col / y1t row
        const float* wf = &wsm[(warp * 2 + 0) * 256];
        const float* wc = &wsm[(warp * 2 + 1) * 256];

        // xpre cooperative prefetch mapping: thread -> (batch, gate, quad)
        const int xb = tid & 63;
        const int xg = tid >> 7;
        const int xq = (tid >> 6) & 1;
        const float* xsrc = g_xpre + (size_t)xb * T_ * 512 + xg * 256 + j0 + xq * 4;
        float* xdst = &xs[(xg * 8 + xq * 4) * 64 + xb];

        unsigned ph = 0;
        float4 xv = __ldcg((const float4*)xsrc);       // prefetch t=0

        for (int t = 0; t < T_; ++t) {
            if (tid == 0 && t > 0) {
                while (ld_acq(&g_cnt1[t - 1]) < L1CTAS) __nanosleep(40);
            }
            __syncthreads();
            // stage prefetched xpre into SMEM
            xdst[0 * 64] = xv.x; xdst[1 * 64] = xv.y; xdst[2 * 64] = xv.z; xdst[3 * 64] = xv.w;
            if (tid == 0) {
                fence_async();
                const float* src = g_y1t + (size_t)t * (H_ * B_);
                mbar_expect(s2u(&mbar[0]), 32768);
                bulk_g2s(s2u(hs), src, 32768, s2u(&mbar[0]));
                mbar_expect(s2u(&mbar[1]), 32768);
                bulk_g2s(s2u(hs) + 32768, src + 8192, 32768, s2u(&mbar[1]));
            }
            // prefetch next step's xpre (independent of everything)
            if (t + 1 < T_) xv = __ldcg((const float4*)(xsrc + (t + 1) * 512));

            float accf0 = 0.f, accf1 = 0.f, accc0 = 0.f, accc1 = 0.f;
#pragma unroll
            for (int c = 0; c < 2; ++c) {
                mbar_wait(s2u(&mbar[c]), ph);
                const float* hp = hs + c * 8192;
                const float* wfp = wf + c * 128;
                const float* wcp = wc + c * 128;
#pragma unroll 8
                for (int k4 = 0; k4 < 128; k4 += 4) {
                    float4 wf4 = *(const float4*)(wfp + k4);
                    float4 wc4 = *(const float4*)(wcp + k4);
#pragma unroll
                    for (int i = 0; i < 4; ++i) {
                        float h0 = hp[(k4 + i) * 64 + lane];
                        float h1 = hp[(k4 + i) * 64 + lane + 32];
                        float wfs = (&wf4.x)[i];
                        float wcs = (&wc4.x)[i];
                        accf0 = fmaf(h0, wfs, accf0);
                        accf1 = fmaf(h1, wfs, accf1);
                        accc0 = fmaf(h0, wcs, accc0);
                        accc1 = fmaf(h1, wcs, accc1);
                    }
                }
            }
            __syncthreads();   // xs visibility for gate math
            float pf0 = accf0 + xs[(0 * 8 + warp) * 64 + lane];
            float pf1 = accf1 + xs[(0 * 8 + warp) * 64 + lane + 32];
            float pc0 = accc0 + xs[(1 * 8 + warp) * 64 + lane];
            float pc1 = accc1 + xs[(1 * 8 + warp) * 64 + lane + 32];
            float f0 = 1.f / (1.f + expf(-pf0));
            float f1 = 1.f / (1.f + expf(-pf1));
            float c0 = tanhf(pc0);
            float c1 = tanhf(pc1);
            float hold0 = hs[j * 64 + lane];
            float hold1 = hs[j * 64 + lane + 32];
            float hn0 = f0 * hold0 + (1.f - f0) * c0;
            float hn1 = f1 * hold1 + (1.f - f1) * c1;
            float* ydst = g_y1t + (size_t)(t + 1) * (H_ * B_) + j * 64;
            ydst[lane] = hn0;
            ydst[lane + 32] = hn1;
            if (t == T_ - 1) {
                out[(size_t)B_ * T_ * H_ + (size_t)lane * H_ + j] = hn0;
                out[(size_t)B_ * T_ * H_ + (size_t)(lane + 32) * H_ + j] = hn1;
            }
            __syncthreads();
            if (tid == 0) { __threadfence(); red_add1(&g_cnt1[t]); }
            ph ^= 1;
        }
    } else {
        // ---------------- Layer-2 CTA: 4 cols, 2 gates, 64 batches, k=512 ----------------
        const int m = cid - L1CTAS;
        const int j0 = m * 4;
        for (int i = tid; i < 8 * 512; i += THREADS) {
            int o = i >> 9, k = i & 511;
            int j = j0 + (o >> 1);
            wsm[i] = (o & 1) ? Wc2[(size_t)k * H_ + j] : Wf2[(size_t)k * H_ + j];
        }
        __syncthreads();

        const int col = warp >> 1;
        const int j = j0 + col;                    // absolute h2 col 0..255
        const int b = (warp & 1) * 32 + lane;
        const float* wf = &wsm[(col * 2 + 0) * 512];
        const float* wc = &wsm[(col * 2 + 1) * 512];
        const float biasf = __ldg(bf2 + j);
        const float biasc = __ldg(bc2 + j);

        unsigned ph = 0;
        for (int u = 0; u < T_; ++u) {
            if (tid == 0) {
                for (;;) {
                    unsigned v1 = ld_acq(&g_cnt1[u]);
                    unsigned v2 = (u > 0) ? ld_acq(&g_cnt2[u - 1]) : L2CTAS;
                    if (v1 >= L1CTAS && v2 >= L2CTAS) break;
                    __nanosleep(40);
                }
            }
            __syncthreads();
            if (tid == 0) {
                fence_async();
                const float* s1 = g_y1t + (size_t)(u + 1) * (H_ * B_);
                const float* s2 = g_h2t[u & 1];
                mbar_expect(s2u(&mbar[0]), 32768);
                bulk_g2s(s2u(hs), s1, 32768, s2u(&mbar[0]));
                mbar_expect(s2u(&mbar[1]), 32768);
                bulk_g2s(s2u(hs) + 32768, s1 + 8192, 32768, s2u(&mbar[1]));
                mbar_expect(s2u(&mbar[2]), 32768);
                bulk_g2s(s2u(hs) + 65536, s2, 32768, s2u(&mbar[2]));
                mbar_expect(s2u(&mbar[3]), 32768);
                bulk_g2s(s2u(hs) + 98304, s2 + 8192, 32768, s2u(&mbar[3]));
            }
            float accf = 0.f, accc = 0.f;
#pragma unroll
            for (int c = 0; c < 4; ++c) {
                mbar_wait(s2u(&mbar[c]), ph);
                const float* hp = hs + c * 8192;
                const float* wfp = wf + c * 128;
                const float* wcp = wc + c * 128;
#pragma unroll 8
                for (int k4 = 0; k4 < 128; k4 += 4) {
                    float4 wf4 = *(const float4*)(wfp + k4);
                    float4 wc4 = *(const float4*)(wcp + k4);
#pragma unroll
                    for (int i = 0; i < 4; ++i) {
                        float hv = hp[(k4 + i) * 64 + b];
                        float wfs = (&wf4.x)[i];
                        float wcs = (&wc4.x)[i];
                        accf = fmaf(hv, wfs, accf);
                        accc = fmaf(hv, wcs, accc);
                    }
                }
            }
            float pf = accf + biasf;
            float pc = accc + biasc;
            float f = 1.f / (1.f + expf(-pf));
            float cc = tanhf(pc);
            float hold = hs[(256 + j) * 64 + b];
            float hn = f * hold + (1.f - f) * cc;
            g_h2t[(u + 1) & 1][j * 64 + b] = hn;
            out[((size_t)b * T_ + u) * H_ + j] = hn;
            if (u == T_ - 1) {
                out[(size_t)B_ * T_ * H_ + (size_t)B_ * H_ + (size_t)b * H_ + j] = hn;
            }
            __syncthreads();
            if (tid == 0) { __threadfence(); red_add1(&g_cnt2[u]); }
            ph ^= 1;
        }
    }
}

// ============================================================
extern "C" void kernel_launch(void* const* d_in, const int* in_sizes, int n_in,
                              void* d_out, int out_size)
{
    const float* x   = (const float*)d_in[0];
    const float* Wf1 = (const float*)d_in[1];
    const float* bf1 = (const float*)d_in[2];
    const float* Wc1 = (const float*)d_in[3];
    const float* bc1 = (const float*)d_in[4];
    const float* Wf2 = (const float*)d_in[5];
    const float* bf2 = (const float*)d_in[6];
    const float* Wc2 = (const float*)d_in[7];
    const float* bc2 = (const float*)d_in[8];
    float* out = (float*)d_out;

    // Opt-in to 128KB dynamic SMEM (first call happens outside graph capture,
    // so the attribute is already set for subsequent captured launches).
    cudaFuncSetAttribute((const void*)recur_kernel,
                         cudaFuncAttributeMaxDynamicSharedMemorySize, 131072);

    init_kernel<<<64, 256>>>();
    xproj_kernel<<<dim3(1024, 8), 256>>>(x, Wf1, bf1, Wc1, bc1);
    recur_kernel<<<NCTA, THREADS, 131072>>>(Wf1, Wc1, Wf2, bf2, Wc2, bc2, out);
}

// round 3
// speedup vs baseline: 2.4377x; 1.2049x over previous
#include <cuda_runtime.h>
#include <cstdint>
#include <cstddef>

// Problem constants
#define B_ 64
#define T_ 1024
#define I_ 128
#define H_ 256

#define L1CTAS 32
#define L2CTAS 64
#define NCTA (L1CTAS + L2CTAS)
#define THREADS 256

#define OUT_Y2 ((size_t)B_ * T_ * H_)

// Inputs: x, Wf1, bf1, Wc1, bc1, Wf2, bf2, Wc2, bc2
// Output: y2 [B,T,H] then hidden [2,B,H]

// -------- device scratch --------
__device__ __align__(16) float g_xpre[(size_t)B_ * T_ * 512];
__device__ __align__(16) float g_y1t[(size_t)(T_ + 1) * H_ * B_];   // [t][j][b]
__device__ __align__(16) float g_h2t[2][H_ * B_];                   // [par][j][b]
__device__ unsigned g_cnt1[T_ + 1];
__device__ unsigned g_cnt2[T_ + 1];

// -------- PTX helpers --------
__device__ __forceinline__ uint32_t s2u(const void* p) {
    return (uint32_t)__cvta_generic_to_shared(p);
}
__device__ __forceinline__ void mbar_init(uint32_t a, uint32_t cnt) {
    asm volatile("mbarrier.init.shared.b64 [%0], %1;" :: "r"(a), "r"(cnt) : "memory");
}
__device__ __forceinline__ void mbar_expect(uint32_t a, uint32_t bytes) {
    asm volatile("mbarrier.arrive.expect_tx.shared.b64 _, [%0], %1;" :: "r"(a), "r"(bytes) : "memory");
}
__device__ __forceinline__ void bulk_g2s(uint32_t dst, const void* src, uint32_t bytes, uint32_t mbar) {
    asm volatile("cp.async.bulk.shared::cluster.global.mbarrier::complete_tx::bytes [%0], [%1], %2, [%3];"
                 :: "r"(dst), "l"(src), "r"(bytes), "r"(mbar) : "memory");
}
__device__ __forceinline__ void mbar_wait(uint32_t a, uint32_t parity) {
    asm volatile("{\n\t"
                 ".reg .pred P;\n\t"
                 "W%=:\n\t"
                 "mbarrier.try_wait.parity.shared.b64 P, [%0], %1, 0x989680;\n\t"
                 "@P bra D%=;\n\t"
                 "bra W%=;\n\t"
                 "D%=:\n\t"
                 "}" :: "r"(a), "r"(parity) : "memory");
}
__device__ __forceinline__ void fence_async() {
    asm volatile("fence.proxy.async.shared::cta;" ::: "memory");
}
__device__ __forceinline__ unsigned ld_acq(const unsigned* p) {
    unsigned v;
    asm volatile("ld.global.acquire.gpu.u32 %0, [%1];" : "=r"(v) : "l"(p) : "memory");
    return v;
}
__device__ __forceinline__ void red_add1(unsigned* p) {
    asm volatile("red.release.gpu.global.add.u32 [%0], %1;" :: "l"(p), "r"(1u) : "memory");
}
// f32x2 packed math
typedef unsigned long long u64;
__device__ __forceinline__ u64 pack2(float x, float y) {
    u64 r; asm("mov.b64 %0, {%1, %2};" : "=l"(r) : "f"(x), "f"(y)); return r;
}
__device__ __forceinline__ void unpack2(u64 v, float& x, float& y) {
    asm("mov.b64 {%0, %1}, %2;" : "=f"(x), "=f"(y) : "l"(v));
}
__device__ __forceinline__ u64 fma2(u64 a, u64 b, u64 c) {
    u64 d; asm("fma.rn.f32x2 %0, %1, %2, %3;" : "=l"(d) : "l"(a), "l"(b), "l"(c)); return d;
}
__device__ __forceinline__ u64 add2(u64 a, u64 b) {
    u64 d; asm("add.rn.f32x2 %0, %1, %2;" : "=l"(d) : "l"(a), "l"(b)); return d;
}
__device__ __forceinline__ float sigm(float x) { return 1.f / (1.f + __expf(-x)); }
__device__ __forceinline__ float tanh_f(float x) { return 1.f - 2.f / (1.f + __expf(2.f * x)); }

// ============================================================
// Phase 1: x-projection GEMM (unchanged)
// ============================================================
__global__ void __launch_bounds__(256) xproj_kernel(
    const float* __restrict__ x,
    const float* __restrict__ Wf1, const float* __restrict__ bf1,
    const float* __restrict__ Wc1, const float* __restrict__ bc1)
{
    __shared__ float As[64][68];
    __shared__ float Bs[64][68];
    const int bm = blockIdx.x;
    const int bn = blockIdx.y;
    const int tid = threadIdx.x;
    const int tx = tid & 15, ty = tid >> 4;

    const float* W; const float* bias; int jb;
    if (bn < 4) { W = Wf1; bias = bf1; jb = bn * 64; }
    else        { W = Wc1; bias = bc1; jb = (bn - 4) * 64; }

    float acc[4][4];
#pragma unroll
    for (int i = 0; i < 4; ++i)
#pragma unroll
        for (int j = 0; j < 4; ++j) acc[i][j] = 0.f;

    for (int k0 = 0; k0 < 128; k0 += 64) {
#pragma unroll
        for (int i = 0; i < 4; ++i) {
            int idx = tid + i * 256;
            int r = idx >> 4, kv = idx & 15;
            float4 v = *(const float4*)(x + (size_t)(bm * 64 + r) * 128 + k0 + kv * 4);
            *(float4*)&As[r][kv * 4] = v;
        }
#pragma unroll
        for (int i = 0; i < 4; ++i) {
            int idx = tid + i * 256;
            int kk = idx >> 4, cv = idx & 15;
            float4 v = *(const float4*)(W + (size_t)(k0 + kk) * 256 + jb + cv * 4);
            *(float4*)&Bs[kk][cv * 4] = v;
        }
        __syncthreads();
#pragma unroll 16
        for (int kk = 0; kk < 64; ++kk) {
            float a0 = As[ty * 4 + 0][kk];
            float a1 = As[ty * 4 + 1][kk];
            float a2 = As[ty * 4 + 2][kk];
            float a3 = As[ty * 4 + 3][kk];
            float4 bv = *(const float4*)&Bs[kk][tx * 4];
            acc[0][0] = fmaf(a0, bv.x, acc[0][0]);
            acc[0][1] = fmaf(a0, bv.y, acc[0][1]);
            acc[0][2] = fmaf(a0, bv.z, acc[0][2]);
            acc[0][3] = fmaf(a0, bv.w, acc[0][3]);
            acc[1][0] = fmaf(a1, bv.x, acc[1][0]);
            acc[1][1] = fmaf(a1, bv.y, acc[1][1]);
            acc[1][2] = fmaf(a1, bv.z, acc[1][2]);
            acc[1][3] = fmaf(a1, bv.w, acc[1][3]);
            acc[2][0] = fmaf(a2, bv.x, acc[2][0]);
            acc[2][1] = fmaf(a2, bv.y, acc[2][1]);
            acc[2][2] = fmaf(a2, bv.z, acc[2][2]);
            acc[2][3] = fmaf(a2, bv.w, acc[2][3]);
            acc[3][0] = fmaf(a3, bv.x, acc[3][0]);
            acc[3][1] = fmaf(a3, bv.y, acc[3][1]);
            acc[3][2] = fmaf(a3, bv.z, acc[3][2]);
            acc[3][3] = fmaf(a3, bv.w, acc[3][3]);
        }
        __syncthreads();
    }
#pragma unroll
    for (int i = 0; i < 4; ++i) {
        int r = bm * 64 + ty * 4 + i;
        float4 o;
        o.x = acc[i][0] + bias[jb + tx * 4 + 0];
        o.y = acc[i][1] + bias[jb + tx * 4 + 1];
        o.z = acc[i][2] + bias[jb + tx * 4 + 2];
        o.w = acc[i][3] + bias[jb + tx * 4 + 3];
        *(float4*)&g_xpre[(size_t)r * 512 + bn * 64 + tx * 4] = o;
    }
}

// ============================================================
__global__ void init_kernel()
{
    int i = blockIdx.x * blockDim.x + threadIdx.x;
    if (i < H_ * B_) {
        g_y1t[i] = 0.f;
        g_h2t[0][i] = 0.f;
    }
    if (i <= T_) { g_cnt1[i] = 0; g_cnt2[i] = 0; }
}

// ============================================================
// Phase 2: persistent recurrence
//   f32x2 gate-pair accumulators, 4 cols/warp, k split across warps
// ============================================================
extern __shared__ __align__(16) float hs[];   // L1: 256*64 (64KB), L2: 512*64 (128KB), [k][b]

__global__ void __launch_bounds__(THREADS, 1) recur_kernel(
    const float* __restrict__ Wf1, const float* __restrict__ Wc1,
    const float* __restrict__ Wf2, const float* __restrict__ bf2,
    const float* __restrict__ Wc2, const float* __restrict__ bc2,
    float* __restrict__ out)
{
    __shared__ u64 wp[2048];                 // packed (wf,wc): L1 [8 cols][256 k], L2 [4 cols][512 k]
    __shared__ float xs[1024];               // L1 xpre staging [gate*8+cl][b]
    __shared__ u64 redbuf[768];              // cross-warp k partial sums
    __shared__ __align__(8) unsigned long long mbar[4];

    const int tid = threadIdx.x;
    const int warp = tid >> 5, lane = tid & 31;
    const int cid = blockIdx.x;

    if (tid == 0) {
#pragma unroll
        for (int i = 0; i < 4; ++i) mbar_init(s2u(&mbar[i]), 1);
    }

    if (cid < L1CTAS) {
        // ======== Layer-1 CTA: 8 cols; warp = (colgroup g, bhalf, khalf) ========
        const int j0 = cid * 8;
        for (int i = tid; i < 2048; i += THREADS) {
            int cl = i >> 8, k = i & 255;
            int j = j0 + cl;
            wp[i] = pack2(Wf1[(size_t)(I_ + k) * H_ + j], Wc1[(size_t)(I_ + k) * H_ + j]);
        }
        __syncthreads();

        const int g = warp >> 2;
        const int bhalf = (warp >> 1) & 1;
        const int khalf = warp & 1;
        const int b = bhalf * 32 + lane;
        const int gb = warp >> 1;                 // g*2 + bhalf

        // xpre prefetch mapping: thread -> (batch, gate, quad)
        const int xb = tid & 63;
        const int xg = tid >> 7;
        const int xq = (tid >> 6) & 1;
        const float* xsrc = g_xpre + (size_t)xb * T_ * 512 + xg * 256 + j0 + xq * 4;
        float* xdst = &xs[(xg * 8 + xq * 4) * 64 + xb];

        const u64* w0 = wp + (g * 4 + 0) * 256 + khalf * 128;
        const u64* w1 = w0 + 256;
        const u64* w2 = w1 + 256;
        const u64* w3 = w2 + 256;
        const float* hp = hs + khalf * 128 * 64;

        unsigned ph = 0;
        float4 xv = __ldcg((const float4*)xsrc);

        for (int t = 0; t < T_; ++t) {
            if (tid == 0 && t > 0) {
                while (ld_acq(&g_cnt1[t - 1]) < L1CTAS) __nanosleep(20);
            }
            __syncthreads();
            xdst[0 * 64] = xv.x; xdst[1 * 64] = xv.y; xdst[2 * 64] = xv.z; xdst[3 * 64] = xv.w;
            if (tid == 0) {
                fence_async();
                const float* src = g_y1t + (size_t)t * (H_ * B_);
                mbar_expect(s2u(&mbar[0]), 32768);
                bulk_g2s(s2u(hs), src, 32768, s2u(&mbar[0]));
                mbar_expect(s2u(&mbar[1]), 32768);
                bulk_g2s(s2u(hs) + 32768, src + 8192, 32768, s2u(&mbar[1]));
            }
            if (t + 1 < T_) xv = __ldcg((const float4*)(xsrc + (size_t)(t + 1) * 512));

            u64 a0e = 0, a0o = 0, a1e = 0, a1o = 0, a2e = 0, a2o = 0, a3e = 0, a3o = 0;
            mbar_wait(s2u(&mbar[khalf]), ph);
#pragma unroll 8
            for (int k2 = 0; k2 < 64; ++k2) {
                int k = k2 * 2;
                float ha = hp[k * 64 + b];
                float hb2 = hp[(k + 1) * 64 + b];
                u64 hha = pack2(ha, ha);
                u64 hhb = pack2(hb2, hb2);
                ulonglong2 wv0 = *(const ulonglong2*)(w0 + k);
                ulonglong2 wv1 = *(const ulonglong2*)(w1 + k);
                ulonglong2 wv2 = *(const ulonglong2*)(w2 + k);
                ulonglong2 wv3 = *(const ulonglong2*)(w3 + k);
                a0e = fma2(hha, wv0.x, a0e); a0o = fma2(hhb, wv0.y, a0o);
                a1e = fma2(hha, wv1.x, a1e); a1o = fma2(hhb, wv1.y, a1o);
                a2e = fma2(hha, wv2.x, a2e); a2o = fma2(hhb, wv2.y, a2o);
                a3e = fma2(hha, wv3.x, a3e); a3o = fma2(hhb, wv3.y, a3o);
            }
            u64 acc0 = add2(a0e, a0o), acc1 = add2(a1e, a1o);
            u64 acc2 = add2(a2e, a2o), acc3 = add2(a3e, a3o);

            if (khalf == 1) {
                redbuf[(gb * 4 + 0) * 32 + lane] = acc0;
                redbuf[(gb * 4 + 1) * 32 + lane] = acc1;
                redbuf[(gb * 4 + 2) * 32 + lane] = acc2;
                redbuf[(gb * 4 + 3) * 32 + lane] = acc3;
            }
            __syncthreads();
            if (khalf == 0) {
                acc0 = add2(acc0, redbuf[(gb * 4 + 0) * 32 + lane]);
                acc1 = add2(acc1, redbuf[(gb * 4 + 1) * 32 + lane]);
                acc2 = add2(acc2, redbuf[(gb * 4 + 2) * 32 + lane]);
                acc3 = add2(acc3, redbuf[(gb * 4 + 3) * 32 + lane]);
                u64 accs[4] = {acc0, acc1, acc2, acc3};
                float* ydst = g_y1t + (size_t)(t + 1) * (H_ * B_);
#pragma unroll
                for (int c = 0; c < 4; ++c) {
                    int cl = g * 4 + c;
                    int jg = j0 + cl;
                    float pf, pc;
                    unpack2(accs[c], pf, pc);
                    pf += xs[cl * 64 + b];
                    pc += xs[(8 + cl) * 64 + b];
                    float f = sigm(pf);
                    float cg = tanh_f(pc);
                    float hold = hs[jg * 64 + b];
                    float hn = fmaf(f, hold - cg, cg);
                    ydst[jg * 64 + b] = hn;
                    if (t == T_ - 1) out[OUT_Y2 + (size_t)b * H_ + jg] = hn;
                }
            }
            __syncthreads();
            if (tid == 0) red_add1(&g_cnt1[t]);
            ph ^= 1;
        }
    } else {
        // ======== Layer-2 CTA: 4 cols; warp = (bhalf, kq) ========
        const int m = cid - L1CTAS;
        const int j0 = m * 4;
        for (int i = tid; i < 2048; i += THREADS) {
            int cl = i >> 9, k = i & 511;
            int j = j0 + cl;
            wp[i] = pack2(Wf2[(size_t)k * H_ + j], Wc2[(size_t)k * H_ + j]);
        }
        __syncthreads();

        const int bhalf = warp >> 2;
        const int kq = warp & 3;
        const int b = bhalf * 32 + lane;

        float biasf[4], biasc[4];
#pragma unroll
        for (int c = 0; c < 4; ++c) {
            biasf[c] = __ldg(bf2 + j0 + c);
            biasc[c] = __ldg(bc2 + j0 + c);
        }

        const u64* w0 = wp + (0) * 512 + kq * 128;
        const u64* w1 = w0 + 512;
        const u64* w2 = w1 + 512;
        const u64* w3 = w2 + 512;
        const float* hp = hs + kq * 128 * 64;

        unsigned ph = 0;
        for (int u = 0; u < T_; ++u) {
            if (tid == 0) {
                for (;;) {
                    unsigned v1 = ld_acq(&g_cnt1[u]);
                    unsigned v2 = (u > 0) ? ld_acq(&g_cnt2[u - 1]) : L2CTAS;
                    if (v1 >= L1CTAS && v2 >= L2CTAS) break;
                    __nanosleep(20);
                }
            }
            __syncthreads();
            if (tid == 0) {
                fence_async();
                const float* s1 = g_y1t + (size_t)(u + 1) * (H_ * B_);
                const float* s2 = g_h2t[u & 1];
                mbar_expect(s2u(&mbar[0]), 32768);
                bulk_g2s(s2u(hs), s1, 32768, s2u(&mbar[0]));
                mbar_expect(s2u(&mbar[1]), 32768);
                bulk_g2s(s2u(hs) + 32768, s1 + 8192, 32768, s2u(&mbar[1]));
                mbar_expect(s2u(&mbar[2]), 32768);
                bulk_g2s(s2u(hs) + 65536, s2, 32768, s2u(&mbar[2]));
                mbar_expect(s2u(&mbar[3]), 32768);
                bulk_g2s(s2u(hs) + 98304, s2 + 8192, 32768, s2u(&mbar[3]));
            }

            u64 a0e = 0, a0o = 0, a1e = 0, a1o = 0, a2e = 0, a2o = 0, a3e = 0, a3o = 0;
            mbar_wait(s2u(&mbar[kq]), ph);
#pragma unroll 8
            for (int k2 = 0; k2 < 64; ++k2) {
                int k = k2 * 2;
                float ha = hp[k * 64 + b];
                float hb2 = hp[(k + 1) * 64 + b];
                u64 hha = pack2(ha, ha);
                u64 hhb = pack2(hb2, hb2);
                ulonglong2 wv0 = *(const ulonglong2*)(w0 + k);
                ulonglong2 wv1 = *(const ulonglong2*)(w1 + k);
                ulonglong2 wv2 = *(const ulonglong2*)(w2 + k);
                ulonglong2 wv3 = *(const ulonglong2*)(w3 + k);
                a0e = fma2(hha, wv0.x, a0e); a0o = fma2(hhb, wv0.y, a0o);
                a1e = fma2(hha, wv1.x, a1e); a1o = fma2(hhb, wv1.y, a1o);
                a2e = fma2(hha, wv2.x, a2e); a2o = fma2(hhb, wv2.y, a2o);
                a3e = fma2(hha, wv3.x, a3e); a3o = fma2(hhb, wv3.y, a3o);
            }
            u64 acc0 = add2(a0e, a0o), acc1 = add2(a1e, a1o);
            u64 acc2 = add2(a2e, a2o), acc3 = add2(a3e, a3o);

            if (kq != 0) {
                int base = ((bhalf * 3 + kq - 1) * 4) * 32 + lane;
                redbuf[base + 0 * 32] = acc0;
                redbuf[base + 1 * 32] = acc1;
                redbuf[base + 2 * 32] = acc2;
                redbuf[base + 3 * 32] = acc3;
            }
            __syncthreads();
            if (kq == 0) {
#pragma unroll
                for (int q = 0; q < 3; ++q) {
                    int base = ((bhalf * 3 + q) * 4) * 32 + lane;
                    acc0 = add2(acc0, redbuf[base + 0 * 32]);
                    acc1 = add2(acc1, redbuf[base + 1 * 32]);
                    acc2 = add2(acc2, redbuf[base + 2 * 32]);
                    acc3 = add2(acc3, redbuf[base + 3 * 32]);
                }
                u64 accs[4] = {acc0, acc1, acc2, acc3};
                float hnv[4];
                float* h2dst = g_h2t[(u + 1) & 1];
#pragma unroll
                for (int c = 0; c < 4; ++c) {
                    int j = j0 + c;
                    float pf, pc;
                    unpack2(accs[c], pf, pc);
                    pf += biasf[c];
                    pc += biasc[c];
                    float f = sigm(pf);
                    float cg = tanh_f(pc);
                    float hold = hs[(256 + j) * 64 + b];
                    float hn = fmaf(f, hold - cg, cg);
                    hnv[c] = hn;
                    h2dst[j * 64 + b] = hn;
                }
                *(float4*)&out[((size_t)b * T_ + u) * H_ + j0] =
                    make_float4(hnv[0], hnv[1], hnv[2], hnv[3]);
                if (u == T_ - 1) {
                    *(float4*)&out[OUT_Y2 + (size_t)B_ * H_ + (size_t)b * H_ + j0] =
                        make_float4(hnv[0], hnv[1], hnv[2], hnv[3]);
                }
            }
            __syncthreads();
            if (tid == 0) red_add1(&g_cnt2[u]);
            ph ^= 1;
        }
    }
}

// ============================================================
extern "C" void kernel_launch(void* const* d_in, const int* in_sizes, int n_in,
                              void* d_out, int out_size)
{
    const float* x   = (const float*)d_in[0];
    const float* Wf1 = (const float*)d_in[1];
    const float* bf1 = (const float*)d_in[2];
    const float* Wc1 = (const float*)d_in[3];
    const float* bc1 = (const float*)d_in[4];
    const float* Wf2 = (const float*)d_in[5];
    const float* bf2 = (const float*)d_in[6];
    const float* Wc2 = (const float*)d_in[7];
    const float* bc2 = (const float*)d_in[8];
    float* out = (float*)d_out;

    cudaFuncSetAttribute((const void*)recur_kernel,
                         cudaFuncAttributeMaxDynamicSharedMemorySize, 131072);

    init_kernel<<<64, 256>>>();
    xproj_kernel<<<dim3(1024, 8), 256>>>(x, Wf1, bf1, Wc1, bc1);
    recur_kernel<<<NCTA, THREADS, 131072>>>(Wf1, Wc1, Wf2, bf2, Wc2, bc2, out);
}

// round 4
// speedup vs baseline: 2.5484x; 1.0454x over previous
#include <cuda_runtime.h>
#include <cstdint>
#include <cstddef>

// Problem constants
#define B_ 64
#define T_ 1024
#define I_ 128
#define H_ 256

#define GRP 2              // batch groups (32 batches each)
#define BG 32              // batches per group
#define L1CTAS_G 32        // L1 CTAs per group (8 cols each)
#define L2CTAS_G 32        // L2 CTAs per group (8 cols each)
#define NCTA ((L1CTAS_G + L2CTAS_G) * GRP)   // 128
#define THREADS 256

#define OUT_Y2 ((size_t)B_ * T_ * H_)

// Inputs: x, Wf1, bf1, Wc1, bc1, Wf2, bf2, Wc2, bc2
// Output: y2 [B,T,H] then hidden [2,B,H]

// -------- device scratch --------
__device__ __align__(16) float g_xpre[(size_t)B_ * T_ * 512];                 // [b][t][512]
__device__ __align__(16) float g_y1t[(size_t)(T_ + 1) * GRP * H_ * BG];       // [t][g][j*32+b']
__device__ __align__(16) float g_h2t[2][GRP][H_ * BG];                        // [par][g][j*32+b']
__device__ unsigned g_cnt1[GRP][T_ + 1];
__device__ unsigned g_cnt2[GRP][T_ + 1];

// -------- PTX helpers --------
__device__ __forceinline__ uint32_t s2u(const void* p) {
    return (uint32_t)__cvta_generic_to_shared(p);
}
__device__ __forceinline__ void mbar_init(uint32_t a, uint32_t cnt) {
    asm volatile("mbarrier.init.shared.b64 [%0], %1;" :: "r"(a), "r"(cnt) : "memory");
}
__device__ __forceinline__ void mbar_expect(uint32_t a, uint32_t bytes) {
    asm volatile("mbarrier.arrive.expect_tx.shared.b64 _, [%0], %1;" :: "r"(a), "r"(bytes) : "memory");
}
__device__ __forceinline__ void bulk_g2s(uint32_t dst, const void* src, uint32_t bytes, uint32_t mbar) {
    asm volatile("cp.async.bulk.shared::cluster.global.mbarrier::complete_tx::bytes [%0], [%1], %2, [%3];"
                 :: "r"(dst), "l"(src), "r"(bytes), "r"(mbar) : "memory");
}
__device__ __forceinline__ void mbar_wait(uint32_t a, uint32_t parity) {
    asm volatile("{\n\t"
                 ".reg .pred P;\n\t"
                 "W%=:\n\t"
                 "mbarrier.try_wait.parity.shared.b64 P, [%0], %1, 0x989680;\n\t"
                 "@P bra D%=;\n\t"
                 "bra W%=;\n\t"
                 "D%=:\n\t"
                 "}" :: "r"(a), "r"(parity) : "memory");
}
__device__ __forceinline__ void fence_async() {
    asm volatile("fence.proxy.async.shared::cta;" ::: "memory");
}
__device__ __forceinline__ unsigned ld_acq(const unsigned* p) {
    unsigned v;
    asm volatile("ld.global.acquire.gpu.u32 %0, [%1];" : "=r"(v) : "l"(p) : "memory");
    return v;
}
__device__ __forceinline__ void red_add1(unsigned* p) {
    asm volatile("red.release.gpu.global.add.u32 [%0], %1;" :: "l"(p), "r"(1u) : "memory");
}
// f32x2 packed math
typedef unsigned long long u64;
__device__ __forceinline__ u64 pack2(float x, float y) {
    u64 r; asm("mov.b64 %0, {%1, %2};" : "=l"(r) : "f"(x), "f"(y)); return r;
}
__device__ __forceinline__ void unpack2(u64 v, float& x, float& y) {
    asm("mov.b64 {%0, %1}, %2;" : "=f"(x), "=f"(y) : "l"(v));
}
__device__ __forceinline__ u64 fma2(u64 a, u64 b, u64 c) {
    u64 d; asm("fma.rn.f32x2 %0, %1, %2, %3;" : "=l"(d) : "l"(a), "l"(b), "l"(c)); return d;
}
__device__ __forceinline__ u64 add2(u64 a, u64 b) {
    u64 d; asm("add.rn.f32x2 %0, %1, %2;" : "=l"(d) : "l"(a), "l"(b)); return d;
}
__device__ __forceinline__ float sigm(float x) { return 1.f / (1.f + __expf(-x)); }
__device__ __forceinline__ float tanh_f(float x) { return 1.f - 2.f / (1.f + __expf(2.f * x)); }

// ============================================================
// Phase 1: x-projection GEMM (unchanged)
// ============================================================
__global__ void __launch_bounds__(256) xproj_kernel(
    const float* __restrict__ x,
    const float* __restrict__ Wf1, const float* __restrict__ bf1,
    const float* __restrict__ Wc1, const float* __restrict__ bc1)
{
    __shared__ float As[64][68];
    __shared__ float Bs[64][68];
    const int bm = blockIdx.x;
    const int bn = blockIdx.y;
    const int tid = threadIdx.x;
    const int tx = tid & 15, ty = tid >> 4;

    const float* W; const float* bias; int jb;
    if (bn < 4) { W = Wf1; bias = bf1; jb = bn * 64; }
    else        { W = Wc1; bias = bc1; jb = (bn - 4) * 64; }

    float acc[4][4];
#pragma unroll
    for (int i = 0; i < 4; ++i)
#pragma unroll
        for (int j = 0; j < 4; ++j) acc[i][j] = 0.f;

    for (int k0 = 0; k0 < 128; k0 += 64) {
#pragma unroll
        for (int i = 0; i < 4; ++i) {
            int idx = tid + i * 256;
            int r = idx >> 4, kv = idx & 15;
            float4 v = *(const float4*)(x + (size_t)(bm * 64 + r) * 128 + k0 + kv * 4);
            *(float4*)&As[r][kv * 4] = v;
        }
#pragma unroll
        for (int i = 0; i < 4; ++i) {
            int idx = tid + i * 256;
            int kk = idx >> 4, cv = idx & 15;
            float4 v = *(const float4*)(W + (size_t)(k0 + kk) * 256 + jb + cv * 4);
            *(float4*)&Bs[kk][cv * 4] = v;
        }
        __syncthreads();
#pragma unroll 16
        for (int kk = 0; kk < 64; ++kk) {
            float a0 = As[ty * 4 + 0][kk];
            float a1 = As[ty * 4 + 1][kk];
            float a2 = As[ty * 4 + 2][kk];
            float a3 = As[ty * 4 + 3][kk];
            float4 bv = *(const float4*)&Bs[kk][tx * 4];
            acc[0][0] = fmaf(a0, bv.x, acc[0][0]);
            acc[0][1] = fmaf(a0, bv.y, acc[0][1]);
            acc[0][2] = fmaf(a0, bv.z, acc[0][2]);
            acc[0][3] = fmaf(a0, bv.w, acc[0][3]);
            acc[1][0] = fmaf(a1, bv.x, acc[1][0]);
            acc[1][1] = fmaf(a1, bv.y, acc[1][1]);
            acc[1][2] = fmaf(a1, bv.z, acc[1][2]);
            acc[1][3] = fmaf(a1, bv.w, acc[1][3]);
            acc[2][0] = fmaf(a2, bv.x, acc[2][0]);
            acc[2][1] = fmaf(a2, bv.y, acc[2][1]);
            acc[2][2] = fmaf(a2, bv.z, acc[2][2]);
            acc[2][3] = fmaf(a2, bv.w, acc[2][3]);
            acc[3][0] = fmaf(a3, bv.x, acc[3][0]);
            acc[3][1] = fmaf(a3, bv.y, acc[3][1]);
            acc[3][2] = fmaf(a3, bv.z, acc[3][2]);
            acc[3][3] = fmaf(a3, bv.w, acc[3][3]);
        }
        __syncthreads();
    }
#pragma unroll
    for (int i = 0; i < 4; ++i) {
        int r = bm * 64 + ty * 4 + i;
        float4 o;
        o.x = acc[i][0] + bias[jb + tx * 4 + 0];
        o.y = acc[i][1] + bias[jb + tx * 4 + 1];
        o.z = acc[i][2] + bias[jb + tx * 4 + 2];
        o.w = acc[i][3] + bias[jb + tx * 4 + 3];
        *(float4*)&g_xpre[(size_t)r * 512 + bn * 64 + tx * 4] = o;
    }
}

// ============================================================
__global__ void init_kernel()
{
    int i = blockIdx.x * blockDim.x + threadIdx.x;      // 16384 threads
    if (i < GRP * H_ * BG) {                            // 16384
        g_y1t[i] = 0.f;                                 // t=0 state
        ((float*)g_h2t)[i] = 0.f;                       // par=0 state
    }
    if (i <= T_) {
        g_cnt1[0][i] = 0; g_cnt1[1][i] = 0;
        g_cnt2[0][i] = 0; g_cnt2[1][i] = 0;
    }
}

// ============================================================
// Phase 2: persistent recurrence, batch-split into 2 groups
// ============================================================
extern __shared__ __align__(16) float hs[];   // [k][b'] b'=32: L1 256*32 (32KB), L2 512*32 (64KB)

__global__ void __launch_bounds__(THREADS, 1) recur_kernel(
    const float* __restrict__ Wf1, const float* __restrict__ Wc1,
    const float* __restrict__ Wf2, const float* __restrict__ bf2,
    const float* __restrict__ Wc2, const float* __restrict__ bc2,
    float* __restrict__ out)
{
    __shared__ u64 wp[4096];                 // packed (wf,wc): L1 [8 cols][256 k], L2 [8 cols][512 k]
    __shared__ float xs[512];                // L1 xpre staging [gate*8+cl][b']
    __shared__ u64 redbuf[768];              // cross-warp k partial sums
    __shared__ __align__(8) unsigned long long mbar[4];

    const int tid = threadIdx.x;
    const int warp = tid >> 5, lane = tid & 31;
    const int cid = blockIdx.x;

    if (tid == 0) {
#pragma unroll
        for (int i = 0; i < 4; ++i) mbar_init(s2u(&mbar[i]), 1);
    }

    if (cid < GRP * L1CTAS_G) {
        // ======== Layer-1 CTA: group g, 8 cols, 32 batches, k=256 ========
        const int g = cid >> 5;
        const int m = cid & 31;
        const int j0 = m * 8;
        for (int i = tid; i < 2048; i += THREADS) {
            int cl = i >> 8, k = i & 255;
            int j = j0 + cl;
            wp[i] = pack2(Wf1[(size_t)(I_ + k) * H_ + j], Wc1[(size_t)(I_ + k) * H_ + j]);
        }
        __syncthreads();

        const int cq = warp >> 1;            // col pair 0..3
        const int khalf = warp & 1;

        // xpre prefetch: tid<128 -> (b'=tid&31, gate=(tid>>5)&1, quad=tid>>6&1)
        const int xb = tid & 31;
        const int xg = (tid >> 5) & 1;
        const int xq = (tid >> 6) & 1;
        const bool xact = tid < 128;
        const float* xsrc = g_xpre + (size_t)(g * BG + xb) * T_ * 512 + xg * 256 + j0 + xq * 4;
        float* xdst = &xs[(xg * 8 + xq * 4) * 32 + xb];

        const u64* w0 = wp + (cq * 2 + 0) * 256 + khalf * 128;
        const u64* w1 = w0 + 256;
        const float* hp = hs + khalf * 128 * 32;
        unsigned* cnt = g_cnt1[g];
        const size_t gslab = (size_t)g * (H_ * BG);

        unsigned ph = 0;
        float4 xv = xact ? __ldcg((const float4*)xsrc) : make_float4(0, 0, 0, 0);

        for (int t = 0; t < T_; ++t) {
            if (tid == 0 && t > 0) {
                while (ld_acq(&cnt[t - 1]) < L1CTAS_G) __nanosleep(20);
            }
            __syncthreads();
            if (xact) { xdst[0] = xv.x; xdst[32] = xv.y; xdst[64] = xv.z; xdst[96] = xv.w; }
            if (tid == 0) {
                fence_async();
                const float* src = g_y1t + (size_t)t * (GRP * H_ * BG) + gslab;
                mbar_expect(s2u(&mbar[0]), 16384);
                bulk_g2s(s2u(hs), src, 16384, s2u(&mbar[0]));
                mbar_expect(s2u(&mbar[1]), 16384);
                bulk_g2s(s2u(hs) + 16384, src + 4096, 16384, s2u(&mbar[1]));
            }
            if (xact && t + 1 < T_) xv = __ldcg((const float4*)(xsrc + (size_t)(t + 1) * 512));

            u64 a0e = 0, a0o = 0, a1e = 0, a1o = 0;
            mbar_wait(s2u(&mbar[khalf]), ph);
#pragma unroll 8
            for (int k2 = 0; k2 < 64; ++k2) {
                int k = k2 * 2;
                float ha = hp[k * 32 + lane];
                float hb2 = hp[(k + 1) * 32 + lane];
                u64 hha = pack2(ha, ha);
                u64 hhb = pack2(hb2, hb2);
                ulonglong2 wv0 = *(const ulonglong2*)(w0 + k);
                ulonglong2 wv1 = *(const ulonglong2*)(w1 + k);
                a0e = fma2(hha, wv0.x, a0e); a0o = fma2(hhb, wv0.y, a0o);
                a1e = fma2(hha, wv1.x, a1e); a1o = fma2(hhb, wv1.y, a1o);
            }
            u64 acc0 = add2(a0e, a0o), acc1 = add2(a1e, a1o);

            if (khalf == 1) {
                redbuf[(cq * 2 + 0) * 32 + lane] = acc0;
                redbuf[(cq * 2 + 1) * 32 + lane] = acc1;
            }
            __syncthreads();
            if (khalf == 0) {
                acc0 = add2(acc0, redbuf[(cq * 2 + 0) * 32 + lane]);
                acc1 = add2(acc1, redbuf[(cq * 2 + 1) * 32 + lane]);
                u64 accs[2] = {acc0, acc1};
                float* ydst = g_y1t + (size_t)(t + 1) * (GRP * H_ * BG) + gslab;
#pragma unroll
                for (int c = 0; c < 2; ++c) {
                    int cl = cq * 2 + c;
                    int jg = j0 + cl;
                    float pf, pc;
                    unpack2(accs[c], pf, pc);
                    pf += xs[cl * 32 + lane];
                    pc += xs[(8 + cl) * 32 + lane];
                    float f = sigm(pf);
                    float cg = tanh_f(pc);
                    float hold = hs[jg * 32 + lane];
                    float hn = fmaf(f, hold - cg, cg);
                    ydst[jg * 32 + lane] = hn;
                    if (t == T_ - 1) out[OUT_Y2 + (size_t)(g * BG + lane) * H_ + jg] = hn;
                }
            }
            __syncthreads();
            if (tid == 0) red_add1(&cnt[t]);
            ph ^= 1;
        }
    } else {
        // ======== Layer-2 CTA: group g, 8 cols, 32 batches, k=512 ========
        const int c2 = cid - GRP * L1CTAS_G;
        const int g = c2 >> 5;
        const int m = c2 & 31;
        const int j0 = m * 8;
        for (int i = tid; i < 4096; i += THREADS) {
            int cl = i >> 9, k = i & 511;
            int j = j0 + cl;
            wp[i] = pack2(Wf2[(size_t)k * H_ + j], Wc2[(size_t)k * H_ + j]);
        }
        __syncthreads();

        const int cg = warp >> 2;            // col quad 0/1
        const int kq = warp & 3;             // k quarter

        float biasf[4], biasc[4];
#pragma unroll
        for (int c = 0; c < 4; ++c) {
            biasf[c] = __ldg(bf2 + j0 + cg * 4 + c);
            biasc[c] = __ldg(bc2 + j0 + cg * 4 + c);
        }

        const u64* w0 = wp + (cg * 4 + 0) * 512 + kq * 128;
        const u64* w1 = w0 + 512;
        const u64* w2 = w1 + 512;
        const u64* w3 = w2 + 512;
        const float* hp = hs + kq * 128 * 32;
        unsigned* cnt1 = g_cnt1[g];
        unsigned* cnt2 = g_cnt2[g];
        const size_t gslab = (size_t)g * (H_ * BG);

        unsigned ph = 0;
        for (int u = 0; u < T_; ++u) {
            if (tid == 0) {
                for (;;) {
                    unsigned v1 = ld_acq(&cnt1[u]);
                    unsigned v2 = (u > 0) ? ld_acq(&cnt2[u - 1]) : L2CTAS_G;
                    if (v1 >= L1CTAS_G && v2 >= L2CTAS_G) break;
                    __nanosleep(20);
                }
            }
            __syncthreads();
            if (tid == 0) {
                fence_async();
                const float* s1 = g_y1t + (size_t)(u + 1) * (GRP * H_ * BG) + gslab;
                const float* s2 = g_h2t[u & 1][g];
                mbar_expect(s2u(&mbar[0]), 16384);
                bulk_g2s(s2u(hs), s1, 16384, s2u(&mbar[0]));
                mbar_expect(s2u(&mbar[1]), 16384);
                bulk_g2s(s2u(hs) + 16384, s1 + 4096, 16384, s2u(&mbar[1]));
                mbar_expect(s2u(&mbar[2]), 16384);
                bulk_g2s(s2u(hs) + 32768, s2, 16384, s2u(&mbar[2]));
                mbar_expect(s2u(&mbar[3]), 16384);
                bulk_g2s(s2u(hs) + 49152, s2 + 4096, 16384, s2u(&mbar[3]));
            }

            u64 a0e = 0, a0o = 0, a1e = 0, a1o = 0, a2e = 0, a2o = 0, a3e = 0, a3o = 0;
            mbar_wait(s2u(&mbar[kq]), ph);
#pragma unroll 8
            for (int k2 = 0; k2 < 64; ++k2) {
                int k = k2 * 2;
                float ha = hp[k * 32 + lane];
                float hb2 = hp[(k + 1) * 32 + lane];
                u64 hha = pack2(ha, ha);
                u64 hhb = pack2(hb2, hb2);
                ulonglong2 wv0 = *(const ulonglong2*)(w0 + k);
                ulonglong2 wv1 = *(const ulonglong2*)(w1 + k);
                ulonglong2 wv2 = *(const ulonglong2*)(w2 + k);
                ulonglong2 wv3 = *(const ulonglong2*)(w3 + k);
                a0e = fma2(hha, wv0.x, a0e); a0o = fma2(hhb, wv0.y, a0o);
                a1e = fma2(hha, wv1.x, a1e); a1o = fma2(hhb, wv1.y, a1o);
                a2e = fma2(hha, wv2.x, a2e); a2o = fma2(hhb, wv2.y, a2o);
                a3e = fma2(hha, wv3.x, a3e); a3o = fma2(hhb, wv3.y, a3o);
            }
            u64 acc0 = add2(a0e, a0o), acc1 = add2(a1e, a1o);
            u64 acc2 = add2(a2e, a2o), acc3 = add2(a3e, a3o);

            if (kq != 0) {
                int base = ((cg * 3 + kq - 1) * 4) * 32 + lane;
                redbuf[base + 0 * 32] = acc0;
                redbuf[base + 1 * 32] = acc1;
                redbuf[base + 2 * 32] = acc2;
                redbuf[base + 3 * 32] = acc3;
            }
            __syncthreads();
            if (kq == 0) {
#pragma unroll
                for (int q = 0; q < 3; ++q) {
                    int base = ((cg * 3 + q) * 4) * 32 + lane;
                    acc0 = add2(acc0, redbuf[base + 0 * 32]);
                    acc1 = add2(acc1, redbuf[base + 1 * 32]);
                    acc2 = add2(acc2, redbuf[base + 2 * 32]);
                    acc3 = add2(acc3, redbuf[base + 3 * 32]);
                }
                u64 accs[4] = {acc0, acc1, acc2, acc3};
                float hnv[4];
                float* h2dst = g_h2t[(u + 1) & 1][g];
#pragma unroll
                for (int c = 0; c < 4; ++c) {
                    int j = j0 + cg * 4 + c;
                    float pf, pc;
                    unpack2(accs[c], pf, pc);
                    pf += biasf[c];
                    pc += biasc[c];
                    float f = sigm(pf);
                    float cgt = tanh_f(pc);
                    float hold = hs[(256 + j) * 32 + lane];
                    float hn = fmaf(f, hold - cgt, cgt);
                    hnv[c] = hn;
                    h2dst[j * 32 + lane] = hn;
                }
                int b = g * BG + lane;
                *(float4*)&out[((size_t)b * T_ + u) * H_ + j0 + cg * 4] =
                    make_float4(hnv[0], hnv[1], hnv[2], hnv[3]);
                if (u == T_ - 1) {
                    *(float4*)&out[OUT_Y2 + (size_t)B_ * H_ + (size_t)b * H_ + j0 + cg * 4] =
                        make_float4(hnv[0], hnv[1], hnv[2], hnv[3]);
                }
            }
            __syncthreads();
            if (tid == 0) red_add1(&cnt2[u]);
            ph ^= 1;
        }
    }
}

// ============================================================
extern "C" void kernel_launch(void* const* d_in, const int* in_sizes, int n_in,
                              void* d_out, int out_size)
{
    const float* x   = (const float*)d_in[0];
    const float* Wf1 = (const float*)d_in[1];
    const float* bf1 = (const float*)d_in[2];
    const float* Wc1 = (const float*)d_in[3];
    const float* bc1 = (const float*)d_in[4];
    const float* Wf2 = (const float*)d_in[5];
    const float* bf2 = (const float*)d_in[6];
    const float* Wc2 = (const float*)d_in[7];
    const float* bc2 = (const float*)d_in[8];
    float* out = (float*)d_out;

    cudaFuncSetAttribute((const void*)recur_kernel,
                         cudaFuncAttributeMaxDynamicSharedMemorySize, 65536);

    init_kernel<<<64, 256>>>();
    xproj_kernel<<<dim3(1024, 8), 256>>>(x, Wf1, bf1, Wc1, bc1);
    recur_kernel<<<NCTA, THREADS, 65536>>>(Wf1, Wc1, Wf2, bf2, Wc2, bc2, out);
}

// round 5
// speedup vs baseline: 3.0768x; 1.2074x over previous
#include <cuda_runtime.h>
#include <cstdint>
#include <cstddef>

// Problem constants
#define B_ 64
#define T_ 1024
#define I_ 128
#define H_ 256

#define GRP 2              // batch groups (32 batches each)
#define BG 32
#define L1CTAS_G 32        // L1 CTAs per group (8 cols each)
#define L2CTAS_G 32        // L2 CTAs per group (8 cols each)
#define NCTA ((L1CTAS_G + L2CTAS_G) * GRP)   // 128
#define THREADS 256

#define OUT_Y2 ((size_t)B_ * T_ * H_)
#define SLAB 8192          // floats per (t, group) state slab: 256 j * 32 b

// State layout: pair-interleaved [j/2][b][2] so (h[2m],h[2m+1]) is one 8-byte word.
__device__ __align__(16) float g_xpre[(size_t)B_ * T_ * 512];
__device__ __align__(16) float g_y1t[(size_t)(T_ + 1) * GRP * SLAB];
__device__ __align__(16) float g_h2t[2][GRP][SLAB];
__device__ unsigned g_cnt1[GRP][T_ + 1];
__device__ unsigned g_cnt2[GRP][T_ + 1];

// -------- PTX helpers --------
__device__ __forceinline__ uint32_t s2u(const void* p) {
    return (uint32_t)__cvta_generic_to_shared(p);
}
__device__ __forceinline__ void mbar_init(uint32_t a, uint32_t cnt) {
    asm volatile("mbarrier.init.shared.b64 [%0], %1;" :: "r"(a), "r"(cnt) : "memory");
}
__device__ __forceinline__ void mbar_expect(uint32_t a, uint32_t bytes) {
    asm volatile("mbarrier.arrive.expect_tx.shared.b64 _, [%0], %1;" :: "r"(a), "r"(bytes) : "memory");
}
__device__ __forceinline__ void bulk_g2s(uint32_t dst, const void* src, uint32_t bytes, uint32_t mbar) {
    asm volatile("cp.async.bulk.shared::cluster.global.mbarrier::complete_tx::bytes [%0], [%1], %2, [%3];"
                 :: "r"(dst), "l"(src), "r"(bytes), "r"(mbar) : "memory");
}
__device__ __forceinline__ void mbar_wait(uint32_t a, uint32_t parity) {
    asm volatile("{\n\t"
                 ".reg .pred P;\n\t"
                 "W%=:\n\t"
                 "mbarrier.try_wait.parity.acquire.cta.shared::cta.b64 P, [%0], %1, 0x989680;\n\t"
                 "@P bra D%=;\n\t"
                 "bra W%=;\n\t"
                 "D%=:\n\t"
                 "}" :: "r"(a), "r"(parity) : "memory");
}
__device__ __forceinline__ void fence_async() {
    asm volatile("fence.proxy.async.shared::cta;" ::: "memory");
}
__device__ __forceinline__ unsigned ld_acq(const unsigned* p) {
    unsigned v;
    asm volatile("ld.global.acquire.gpu.u32 %0, [%1];" : "=r"(v) : "l"(p) : "memory");
    return v;
}
__device__ __forceinline__ void red_add1(unsigned* p) {
    asm volatile("red.release.gpu.global.add.u32 [%0], %1;" :: "l"(p), "r"(1u) : "memory");
}
typedef unsigned long long u64;
__device__ __forceinline__ void unpack2(u64 v, float& x, float& y) {
    asm("mov.b64 {%0, %1}, %2;" : "=f"(x), "=f"(y) : "l"(v));
}
__device__ __forceinline__ u64 fma2(u64 a, u64 b, u64 c) {
    u64 d; asm("fma.rn.f32x2 %0, %1, %2, %3;" : "=l"(d) : "l"(a), "l"(b), "l"(c)); return d;
}
__device__ __forceinline__ u64 add2(u64 a, u64 b) {
    u64 d; asm("add.rn.f32x2 %0, %1, %2;" : "=l"(d) : "l"(a), "l"(b)); return d;
}
__device__ __forceinline__ float sigm(float x) { return 1.f / (1.f + __expf(-x)); }
__device__ __forceinline__ float tanh_f(float x) { return 1.f - 2.f / (1.f + __expf(2.f * x)); }

// ============================================================
// Phase 1: x-projection GEMM (unchanged)
// ============================================================
__global__ void __launch_bounds__(256) xproj_kernel(
    const float* __restrict__ x,
    const float* __restrict__ Wf1, const float* __restrict__ bf1,
    const float* __restrict__ Wc1, const float* __restrict__ bc1)
{
    __shared__ float As[64][68];
    __shared__ float Bs[64][68];
    const int bm = blockIdx.x;
    const int bn = blockIdx.y;
    const int tid = threadIdx.x;
    const int tx = tid & 15, ty = tid >> 4;

    const float* W; const float* bias; int jb;
    if (bn < 4) { W = Wf1; bias = bf1; jb = bn * 64; }
    else        { W = Wc1; bias = bc1; jb = (bn - 4) * 64; }

    float acc[4][4];
#pragma unroll
    for (int i = 0; i < 4; ++i)
#pragma unroll
        for (int j = 0; j < 4; ++j) acc[i][j] = 0.f;

    for (int k0 = 0; k0 < 128; k0 += 64) {
#pragma unroll
        for (int i = 0; i < 4; ++i) {
            int idx = tid + i * 256;
            int r = idx >> 4, kv = idx & 15;
            float4 v = *(const float4*)(x + (size_t)(bm * 64 + r) * 128 + k0 + kv * 4);
            *(float4*)&As[r][kv * 4] = v;
        }
#pragma unroll
        for (int i = 0; i < 4; ++i) {
            int idx = tid + i * 256;
            int kk = idx >> 4, cv = idx & 15;
            float4 v = *(const float4*)(W + (size_t)(k0 + kk) * 256 + jb + cv * 4);
            *(float4*)&Bs[kk][cv * 4] = v;
        }
        __syncthreads();
#pragma unroll 16
        for (int kk = 0; kk < 64; ++kk) {
            float a0 = As[ty * 4 + 0][kk];
            float a1 = As[ty * 4 + 1][kk];
            float a2 = As[ty * 4 + 2][kk];
            float a3 = As[ty * 4 + 3][kk];
            float4 bv = *(const float4*)&Bs[kk][tx * 4];
            acc[0][0] = fmaf(a0, bv.x, acc[0][0]);
            acc[0][1] = fmaf(a0, bv.y, acc[0][1]);
            acc[0][2] = fmaf(a0, bv.z, acc[0][2]);
            acc[0][3] = fmaf(a0, bv.w, acc[0][3]);
            acc[1][0] = fmaf(a1, bv.x, acc[1][0]);
            acc[1][1] = fmaf(a1, bv.y, acc[1][1]);
            acc[1][2] = fmaf(a1, bv.z, acc[1][2]);
            acc[1][3] = fmaf(a1, bv.w, acc[1][3]);
            acc[2][0] = fmaf(a2, bv.x, acc[2][0]);
            acc[2][1] = fmaf(a2, bv.y, acc[2][1]);
            acc[2][2] = fmaf(a2, bv.z, acc[2][2]);
            acc[2][3] = fmaf(a2, bv.w, acc[2][3]);
            acc[3][0] = fmaf(a3, bv.x, acc[3][0]);
            acc[3][1] = fmaf(a3, bv.y, acc[3][1]);
            acc[3][2] = fmaf(a3, bv.z, acc[3][2]);
            acc[3][3] = fmaf(a3, bv.w, acc[3][3]);
        }
        __syncthreads();
    }
#pragma unroll
    for (int i = 0; i < 4; ++i) {
        int r = bm * 64 + ty * 4 + i;
        float4 o;
        o.x = acc[i][0] + bias[jb + tx * 4 + 0];
        o.y = acc[i][1] + bias[jb + tx * 4 + 1];
        o.z = acc[i][2] + bias[jb + tx * 4 + 2];
        o.w = acc[i][3] + bias[jb + tx * 4 + 3];
        *(float4*)&g_xpre[(size_t)r * 512 + bn * 64 + tx * 4] = o;
    }
}

// ============================================================
__global__ void init_kernel()
{
    int i = blockIdx.x * blockDim.x + threadIdx.x;      // 16384 threads
    if (i < GRP * SLAB) {
        g_y1t[i] = 0.f;
        ((float*)g_h2t)[i] = 0.f;
    }
    if (i <= T_) {
        g_cnt1[0][i] = 0; g_cnt1[1][i] = 0;
        g_cnt2[0][i] = 0; g_cnt2[1][i] = 0;
    }
}

// ============================================================
// Phase 2: persistent recurrence
// ============================================================
extern __shared__ __align__(16) float hs[];
// L1: hs[0..8192)   = h1 state, 4 chunks of 2048 floats (8KB)
// L2: hs[0..8192)   = ybuf0, [8192..16384) = ybuf1, [16384..24576) = h2buf

__global__ void __launch_bounds__(THREADS, 1) recur_kernel(
    const float* __restrict__ Wf1, const float* __restrict__ Wc1,
    const float* __restrict__ Wf2, const float* __restrict__ bf2,
    const float* __restrict__ Wc2, const float* __restrict__ bc2,
    float* __restrict__ out)
{
    __shared__ float wsm[8192];              // 32KB weights (L1 uses 16KB)
    __shared__ float xs[512];                // L1 xpre staging
    __shared__ u64 redbuf[1536];             // 12KB cross-kq partials
    __shared__ __align__(8) unsigned long long mbar[4];

    const int tid = threadIdx.x;
    const int warp = tid >> 5, lane = tid & 31;
    const int cid = blockIdx.x;
    const int kq = warp >> 1;                // k quarter 0..3
    const int cg = warp & 1;                 // col half (4 cols each)

    if (cid < GRP * L1CTAS_G) {
        // ================= Layer-1 CTA =================
        const int g = cid >> 5;
        const int m = cid & 31;
        const int j0 = m * 8;
        for (int i = tid; i < 4096; i += THREADS) {
            int cl = i >> 9, gg = (i >> 8) & 1, k = i & 255;
            const float* W = gg ? Wc1 : Wf1;
            wsm[i] = W[(size_t)(I_ + k) * H_ + (j0 + cl)];
        }
        if (tid == 0) {
#pragma unroll
            for (int i = 0; i < 4; ++i) mbar_init(s2u(&mbar[i]), 1);
        }
        __syncthreads();

        // xpre staging mapping
        const int xb = tid & 31;
        const int xg = (tid >> 5) & 1;
        const int xq = (tid >> 6) & 1;
        const bool xact = tid < 128;
        const float* xsrc = g_xpre + (size_t)(g * BG + xb) * T_ * 512 + xg * 256 + j0 + xq * 4;
        float* xdst = &xs[(xg * 8 + xq * 4) * 32 + xb];

        const u64* hq = (const u64*)hs + kq * 1024;
        unsigned* cnt = g_cnt1[g];
        const size_t gslab = (size_t)g * SLAB;

        unsigned ph = 0;
        float4 xv = xact ? __ldcg((const float4*)xsrc) : make_float4(0, 0, 0, 0);

        for (int t = 0; t < T_; ++t) {
            // per-chunk issuer: lane 0 of even warp issues chunk kq
            if (lane == 0 && cg == 0) {
                if (t > 0) { while (ld_acq(&cnt[t - 1]) < L1CTAS_G) __nanosleep(20); }
                fence_async();
                uint32_t mb = s2u(&mbar[kq]);
                mbar_expect(mb, 8192);
                bulk_g2s(s2u(hs) + kq * 8192,
                         g_y1t + (size_t)t * (GRP * SLAB) + gslab + kq * 2048, 8192, mb);
            }
            if (xact) { xdst[0] = xv.x; xdst[32] = xv.y; xdst[64] = xv.z; xdst[96] = xv.w; }
            if (xact && t + 1 < T_) xv = __ldcg((const float4*)(xsrc + (size_t)(t + 1) * 512));

            u64 af[4] = {0, 0, 0, 0}, ac[4] = {0, 0, 0, 0};
            mbar_wait(s2u(&mbar[kq]), ph);
#pragma unroll 8
            for (int i = 0; i < 16; ++i) {
                u64 h0 = hq[(2 * i) * 32 + lane];
                u64 h1 = hq[(2 * i + 1) * 32 + lane];
#pragma unroll
                for (int c = 0; c < 4; ++c) {
                    ulonglong2 wf = *(const ulonglong2*)&wsm[(cg * 4 + c) * 512 + kq * 64 + i * 4];
                    ulonglong2 wc = *(const ulonglong2*)&wsm[(cg * 4 + c) * 512 + 256 + kq * 64 + i * 4];
                    af[c] = fma2(h0, wf.x, af[c]); af[c] = fma2(h1, wf.y, af[c]);
                    ac[c] = fma2(h0, wc.x, ac[c]); ac[c] = fma2(h1, wc.y, ac[c]);
                }
            }
            if (kq != 0) {
                int q = kq - 1;
#pragma unroll
                for (int c = 0; c < 4; ++c) {
                    redbuf[((cg * 3 + q) * 8 + c * 2 + 0) * 32 + lane] = af[c];
                    redbuf[((cg * 3 + q) * 8 + c * 2 + 1) * 32 + lane] = ac[c];
                }
            }
            __syncthreads();
            if (kq == 0) {
#pragma unroll
                for (int q = 0; q < 3; ++q)
#pragma unroll
                    for (int c = 0; c < 4; ++c) {
                        af[c] = add2(af[c], redbuf[((cg * 3 + q) * 8 + c * 2 + 0) * 32 + lane]);
                        ac[c] = add2(ac[c], redbuf[((cg * 3 + q) * 8 + c * 2 + 1) * 32 + lane]);
                    }
                float hn[4];
#pragma unroll
                for (int c = 0; c < 4; ++c) {
                    int cl = cg * 4 + c;
                    int j = j0 + cl;
                    float lo, hi;
                    unpack2(af[c], lo, hi);
                    float pf = lo + hi + xs[cl * 32 + lane];
                    unpack2(ac[c], lo, hi);
                    float pc = lo + hi + xs[(8 + cl) * 32 + lane];
                    float f = sigm(pf);
                    float cgt = tanh_f(pc);
                    float hold = hs[(j >> 1) * 64 + lane * 2 + (j & 1)];
                    hn[c] = fmaf(f, hold - cgt, cgt);
                }
                float* ydst = g_y1t + (size_t)(t + 1) * (GRP * SLAB) + gslab + (size_t)(j0 + cg * 4) * 32;
                *(float2*)&ydst[lane * 2] = make_float2(hn[0], hn[1]);
                *(float2*)&ydst[64 + lane * 2] = make_float2(hn[2], hn[3]);
                if (t == T_ - 1) {
                    *(float4*)&out[OUT_Y2 + (size_t)(g * BG + lane) * H_ + j0 + cg * 4] =
                        make_float4(hn[0], hn[1], hn[2], hn[3]);
                }
            }
            __syncthreads();
            if (tid == 0) red_add1(&cnt[t]);
            ph ^= 1;
        }
    } else {
        // ================= Layer-2 CTA =================
        const int c2 = cid - GRP * L1CTAS_G;
        const int g = c2 >> 5;
        const int m = c2 & 31;
        const int j0 = m * 8;
        for (int i = tid; i < 8192; i += THREADS) {
            int cl = i >> 10, gg = (i >> 9) & 1, k = i & 511;
            const float* W = gg ? Wc2 : Wf2;
            wsm[i] = W[(size_t)k * H_ + (j0 + cl)];
        }
        if (tid == 0) {
#pragma unroll
            for (int i = 0; i < 4; ++i) mbar_init(s2u(&mbar[i]), 1);
        }
        __syncthreads();

        float bf[4], bc[4];
#pragma unroll
        for (int c = 0; c < 4; ++c) {
            bf[c] = __ldg(bf2 + j0 + cg * 4 + c);
            bc[c] = __ldg(bc2 + j0 + cg * 4 + c);
        }

        const u64* hsu = (const u64*)hs;
        unsigned* cnt1p = g_cnt1[g];
        unsigned* cnt2p = g_cnt2[g];
        const size_t gslab = (size_t)g * SLAB;

        // pre-loop: prefetch y(0) into ybuf0
        if (tid == 160) {
            while (ld_acq(&cnt1p[0]) < L1CTAS_G) __nanosleep(40);
            fence_async();
            mbar_expect(s2u(&mbar[0]), 32768);
            bulk_g2s(s2u(hs), g_y1t + (size_t)1 * (GRP * SLAB) + gslab, 32768, s2u(&mbar[0]));
        }

        unsigned ph = 0;
        unsigned phy[2] = {0, 0};
        for (int u = 0; u < T_; ++u) {
            // h2 chunk issuers (lane0 of each h2 warp-pair)
            if (tid == 128) {
                if (u > 0) { while (ld_acq(&cnt2p[u - 1]) < L2CTAS_G) __nanosleep(20); }
                fence_async();
                mbar_expect(s2u(&mbar[2]), 16384);
                bulk_g2s(s2u(hs) + 65536, g_h2t[u & 1][g], 16384, s2u(&mbar[2]));
            }
            if (tid == 192) {
                if (u > 0) { while (ld_acq(&cnt2p[u - 1]) < L2CTAS_G) __nanosleep(20); }
                fence_async();
                mbar_expect(s2u(&mbar[3]), 16384);
                bulk_g2s(s2u(hs) + 65536 + 16384, (const float*)g_h2t[u & 1][g] + 4096, 16384, s2u(&mbar[3]));
            }
            // y prefetch for u+1
            if (tid == 160 && u + 1 < T_) {
                while (ld_acq(&cnt1p[u + 1]) < L1CTAS_G) __nanosleep(20);
                fence_async();
                uint32_t mb = s2u(&mbar[(u + 1) & 1]);
                mbar_expect(mb, 32768);
                bulk_g2s(s2u(hs) + ((u + 1) & 1) * 32768,
                         g_y1t + (size_t)(u + 2) * (GRP * SLAB) + gslab, 32768, mb);
            }

            u64 af[4] = {0, 0, 0, 0}, ac[4] = {0, 0, 0, 0};
            const u64* hq;
            if (kq < 2) {
                int bi = u & 1;
                mbar_wait(s2u(&mbar[bi]), phy[bi]);
                phy[bi] ^= 1;
                hq = hsu + bi * 4096 + kq * 2048;
            } else {
                mbar_wait(s2u(&mbar[kq]), ph);
                hq = hsu + 8192 + (kq - 2) * 2048;
            }
#pragma unroll 8
            for (int i = 0; i < 32; ++i) {
                u64 h0 = hq[(2 * i) * 32 + lane];
                u64 h1 = hq[(2 * i + 1) * 32 + lane];
#pragma unroll
                for (int c = 0; c < 4; ++c) {
                    ulonglong2 wf = *(const ulonglong2*)&wsm[(cg * 4 + c) * 1024 + kq * 128 + i * 4];
                    ulonglong2 wc = *(const ulonglong2*)&wsm[(cg * 4 + c) * 1024 + 512 + kq * 128 + i * 4];
                    af[c] = fma2(h0, wf.x, af[c]); af[c] = fma2(h1, wf.y, af[c]);
                    ac[c] = fma2(h0, wc.x, ac[c]); ac[c] = fma2(h1, wc.y, ac[c]);
                }
            }
            if (kq != 0) {
                int q = kq - 1;
#pragma unroll
                for (int c = 0; c < 4; ++c) {
                    redbuf[((cg * 3 + q) * 8 + c * 2 + 0) * 32 + lane] = af[c];
                    redbuf[((cg * 3 + q) * 8 + c * 2 + 1) * 32 + lane] = ac[c];
                }
            }
            __syncthreads();
            if (kq == 0) {
#pragma unroll
                for (int q = 0; q < 3; ++q)
#pragma unroll
                    for (int c = 0; c < 4; ++c) {
                        af[c] = add2(af[c], redbuf[((cg * 3 + q) * 8 + c * 2 + 0) * 32 + lane]);
                        ac[c] = add2(ac[c], redbuf[((cg * 3 + q) * 8 + c * 2 + 1) * 32 + lane]);
                    }
                float hn[4];
#pragma unroll
                for (int c = 0; c < 4; ++c) {
                    int j = j0 + cg * 4 + c;
                    float lo, hi;
                    unpack2(af[c], lo, hi);
                    float pf = lo + hi + bf[c];
                    unpack2(ac[c], lo, hi);
                    float pc = lo + hi + bc[c];
                    float f = sigm(pf);
                    float cgt = tanh_f(pc);
                    float hold = hs[16384 + (j >> 1) * 64 + lane * 2 + (j & 1)];
                    hn[c] = fmaf(f, hold - cgt, cgt);
                }
                float* h2dst = g_h2t[(u + 1) & 1][g] + (size_t)(j0 + cg * 4) * 32;
                *(float2*)&h2dst[lane * 2] = make_float2(hn[0], hn[1]);
                *(float2*)&h2dst[64 + lane * 2] = make_float2(hn[2], hn[3]);
                int b = g * BG + lane;
                *(float4*)&out[((size_t)b * T_ + u) * H_ + j0 + cg * 4] =
                    make_float4(hn[0], hn[1], hn[2], hn[3]);
                if (u == T_ - 1) {
                    *(float4*)&out[OUT_Y2 + (size_t)B_ * H_ + (size_t)b * H_ + j0 + cg * 4] =
                        make_float4(hn[0], hn[1], hn[2], hn[3]);
                }
            }
            __syncthreads();
            if (tid == 0) red_add1(&cnt2p[u]);
            ph ^= 1;
        }
    }
}

// ============================================================
extern "C" void kernel_launch(void* const* d_in, const int* in_sizes, int n_in,
                              void* d_out, int out_size)
{
    const float* x   = (const float*)d_in[0];
    const float* Wf1 = (const float*)d_in[1];
    const float* bf1 = (const float*)d_in[2];
    const float* Wc1 = (const float*)d_in[3];
    const float* bc1 = (const float*)d_in[4];
    const float* Wf2 = (const float*)d_in[5];
    const float* bf2 = (const float*)d_in[6];
    const float* Wc2 = (const float*)d_in[7];
    const float* bc2 = (const float*)d_in[8];
    float* out = (float*)d_out;

    cudaFuncSetAttribute((const void*)recur_kernel,
                         cudaFuncAttributeMaxDynamicSharedMemorySize, 98304);

    init_kernel<<<64, 256>>>();
    xproj_kernel<<<dim3(1024, 8), 256>>>(x, Wf1, bf1, Wc1, bc1);
    recur_kernel<<<NCTA, THREADS, 98304>>>(Wf1, Wc1, Wf2, bf2, Wc2, bc2, out);
}